// round 10
// baseline (speedup 1.0000x reference)
#include <cuda_runtime.h>
#include <cuda_fp16.h>
#include <cstdint>

// Problem constants
#define NROWS 8192          // n = 2*B
#define BROWS 4096          // B
#define DDIM  256           // feature dim
#define BLK   128           // tile edge
#define NT    64            // NROWS/BLK
#define NTRI  (NT*(NT+1)/2) // 2080 upper-triangular tiles
#define KC    64            // k columns per chunk (128B of fp16)
#define NCH   (DDIM/KC)     // 4 chunks
#define ROWB  144           // smem row stride bytes (128B data + 16B pad)
#define MATB  (BLK*ROWB)    // 18432 B per matrix buffer
#define STAGEB (2*MATB)     // 36864 B per stage (A, B)
#define NSTAGE 3
#define DYN_SMEM (NSTAGE*STAGEB) // 110592 B
#define PREPB 256           // prep blocks

// Device scratch (no allocations allowed)
__device__ float  g_sq[NROWS];
__device__ float  g_colpart[PREPB][DDIM];
__device__ double g_s1part[PREPB];
__device__ double g_result;
__device__ float  g_scale;     // 1/(16*bandwidth)
__device__ __half g_h[NROWS * DDIM];
__device__ unsigned int g_prep_count = 0;
__device__ unsigned int g_pair_count = 0;

// ---------------------------------------------------------------------------
__device__ __forceinline__ uint32_t smem_u32(const void* p) {
    uint32_t a;
    asm("{ .reg .u64 t; cvta.to.shared.u64 t, %1; cvt.u32.u64 %0, t; }"
        : "=r"(a) : "l"(p));
    return a;
}

__device__ __forceinline__ void ldsm4(uint32_t* r, uint32_t addr) {
    asm volatile("ldmatrix.sync.aligned.m8n8.x4.shared.b16 {%0,%1,%2,%3}, [%4];"
                 : "=r"(r[0]), "=r"(r[1]), "=r"(r[2]), "=r"(r[3]) : "r"(addr));
}

// fp16-accumulator MMA: acc = 2x b32 regs (half2 pairs)
__device__ __forceinline__ void mma16816h(uint32_t* c, const uint32_t* a,
                                          uint32_t b0, uint32_t b1) {
    asm volatile(
        "mma.sync.aligned.m16n8k16.row.col.f16.f16.f16.f16 "
        "{%0,%1}, {%2,%3,%4,%5}, {%6,%7}, {%0,%1};"
        : "+r"(c[0]), "+r"(c[1])
        : "r"(a[0]), "r"(a[1]), "r"(a[2]), "r"(a[3]), "r"(b0), "r"(b1));
}

__device__ __forceinline__ float ex2f(float x) {
    float r;
    asm("ex2.approx.ftz.f32 %0, %1;" : "=f"(r) : "f"(x));
    return r;
}

#define CP_ASYNC16(dst, src) \
    asm volatile("cp.async.cg.shared.global [%0], [%1], 16;" \
                 :: "r"(dst), "l"(src) : "memory")
#define CP_COMMIT() asm volatile("cp.async.commit_group;" ::: "memory")
#define CP_WAIT1()  asm volatile("cp.async.wait_group 1;" ::: "memory")

// ---------------------------------------------------------------------------
// Fused prep: row norms, per-block column partials + s1 partials, fp16 cast.
// LAST block reduces partials -> bandwidth -> g_scale, zeroes g_result.
__global__ void prep_kernel(const float* __restrict__ src,
                            const float* __restrict__ tgt) {
    __shared__ float  csum_s[8][DDIM];
    __shared__ double s1_s[8];
    __shared__ double red_d[256];
    __shared__ bool   is_last;

    int tid  = threadIdx.x;
    int lane = tid & 31;
    int w    = tid >> 5;
    int b    = blockIdx.x;

    float csum[8] = {0, 0, 0, 0, 0, 0, 0, 0};
    double s1 = 0.0;

    #pragma unroll
    for (int i = 0; i < 4; i++) {
        int r = b * 32 + w * 4 + i;
        const float2* row = (const float2*)((r < BROWS)
                            ? (src + (size_t)r * DDIM)
                            : (tgt + (size_t)(r - BROWS) * DDIM));
        float sq = 0.0f;
        #pragma unroll
        for (int k = 0; k < 4; k++) {
            int idx = lane + 32 * k;            // float2 index 0..127
            float2 x = row[idx];
            sq = fmaf(x.x, x.x, sq);
            sq = fmaf(x.y, x.y, sq);
            csum[2 * k]     += x.x;
            csum[2 * k + 1] += x.y;
            ((half2*)(g_h + (size_t)r * DDIM))[idx] = __floats2half2_rn(x.x, x.y);
        }
        #pragma unroll
        for (int s = 16; s > 0; s >>= 1) sq += __shfl_xor_sync(0xFFFFFFFFu, sq, s);
        if (lane == 0) { g_sq[r] = sq; s1 += (double)sq; }
    }

    #pragma unroll
    for (int k = 0; k < 4; k++) {
        csum_s[w][64 * k + 2 * lane]     = csum[2 * k];
        csum_s[w][64 * k + 2 * lane + 1] = csum[2 * k + 1];
    }
    if (lane == 0) s1_s[w] = s1;
    __syncthreads();

    float t = 0.0f;
    #pragma unroll
    for (int w2 = 0; w2 < 8; w2++) t += csum_s[w2][tid];
    g_colpart[b][tid] = t;
    if (tid == 0) {
        double bs1 = 0.0;
        #pragma unroll
        for (int w2 = 0; w2 < 8; w2++) bs1 += s1_s[w2];
        g_s1part[b] = bs1;
    }

    __threadfence();
    __syncthreads();
    if (tid == 0) {
        unsigned int old = atomicInc(&g_prep_count, PREPB - 1);
        is_last = (old == PREPB - 1);
    }
    __syncthreads();
    if (!is_last) return;
    __threadfence();

    float cs = 0.0f;
    for (int b2 = 0; b2 < PREPB; b2++) cs += g_colpart[b2][tid];
    double ssq = (double)cs * (double)cs;
    double s1v = g_s1part[tid];

    red_d[tid] = ssq;
    __syncthreads();
    #pragma unroll
    for (int s = 128; s > 0; s >>= 1) {
        if (tid < s) red_d[tid] += red_d[tid + s];
        __syncthreads();
    }
    double ss = red_d[0];
    __syncthreads();
    red_d[tid] = s1v;
    __syncthreads();
    #pragma unroll
    for (int s = 128; s > 0; s >>= 1) {
        if (tid < s) red_d[tid] += red_d[tid + s];
        __syncthreads();
    }
    if (tid == 0) {
        double S1 = red_d[0];
        const double n = (double)NROWS;
        double sum_l2 = 2.0 * n * S1 - 2.0 * ss;
        double bw = sum_l2 / (n * n - n) / 4.0;   // / KERNEL_MUL^(KERNEL_NUM/2)
        g_scale = (float)(1.0 / (bw * 16.0));     // largest sigma = bw*2^4
        g_result = 0.0;
    }
}

// ---------------------------------------------------------------------------
// Issue 8 cp.async (16B) per thread: one KC=64 chunk of A and B fp16 tiles.
__device__ __forceinline__ void prefetch_chunk(
    uint32_t sbase, const __half* A, const __half* B, int k0, int tid) {
    #pragma unroll
    for (int l = 0; l < 4; l++) {
        int f   = tid + l * 256;      // 0..1023
        int r   = f >> 3;             // row 0..127
        int c16 = f & 7;              // 16B group within 128B row
        uint32_t so = (uint32_t)r * ROWB + (uint32_t)c16 * 16;
        size_t  go = (size_t)r * DDIM + k0 + c16 * 8;
        CP_ASYNC16(sbase + so,        (const void*)(A + go));
        CP_ASYNC16(sbase + MATB + so, (const void*)(B + go));
    }
}

// ---------------------------------------------------------------------------
// HMMA pair kernel: 128x128 tile per CTA, fp16 mma with fp16 accumulators,
// double-buffered fragments (software-pipelined LDSM under MMA),
// 3-stage cp.async ring; fused finalize in the last CTA.
__global__ void __launch_bounds__(256, 2)
pair10_kernel(float* __restrict__ out) {
    extern __shared__ __align__(16) char dyn[];
    __shared__ float sqa[BLK];
    __shared__ float sqb[BLK];

    int tid  = threadIdx.x;
    int lane = tid & 31;
    int wid  = tid >> 5;
    int wy   = wid >> 2;      // 0..1
    int wx   = wid & 3;       // 0..3

    // Closed-form triangular decode: bi = row of tile, bj >= bi
    int rem = blockIdx.x;
    int bi = (int)((2.0f * NT + 1.0f
              - sqrtf((float)((2 * NT + 1) * (2 * NT + 1) - 8 * rem))) * 0.5f);
    while (bi * NT - bi * (bi - 1) / 2 > rem) bi--;
    while ((bi + 1) * NT - (bi + 1) * bi / 2 <= rem) bi++;
    int bj = bi + rem - (bi * NT - bi * (bi - 1) / 2);

    const __half* A = g_h + (size_t)bi * BLK * DDIM;
    const __half* B = g_h + (size_t)bj * BLK * DDIM;

    uint32_t dynb = smem_u32(dyn);

    // Prologue: 2 chunks in flight
    prefetch_chunk(dynb + 0 * STAGEB, A, B, 0, tid);
    CP_COMMIT();
    prefetch_chunk(dynb + 1 * STAGEB, A, B, KC, tid);
    CP_COMMIT();

    if (tid < BLK) {
        sqa[tid] = g_sq[bi * BLK + tid];
        sqb[tid] = g_sq[bj * BLK + tid];
    }

    // fp16 accumulators: 2x b32 per (mt,nt)
    uint32_t acc[4][4][2];
    #pragma unroll
    for (int mt = 0; mt < 4; mt++)
        #pragma unroll
        for (int nt = 0; nt < 4; nt++) {
            acc[mt][nt][0] = 0u;
            acc[mt][nt][1] = 0u;
        }

    // Per-lane ldmatrix offsets (bytes) within a matrix buffer
    uint32_t a_off = (uint32_t)(wy * 64 + (lane & 15)) * ROWB + ((lane >> 4) << 4);
    uint32_t b_off = (uint32_t)(wx * 32 + (lane & 7) + ((lane >> 4) << 3)) * ROWB
                   + (((lane >> 3) & 1) << 4);

    uint32_t aF[2][4][4];   // double-buffered A fragments
    uint32_t bF[2][2][4];   // double-buffered B fragments

    int stage = 0;
    for (int c = 0; c < NCH; c++) {
        CP_WAIT1();              // chunk c complete (<=1 younger group pending)
        __syncthreads();         // chunk c visible; stage c+2 free
        if (c + 2 < NCH) {
            int pstage = stage + 2;
            if (pstage >= NSTAGE) pstage -= NSTAGE;
            prefetch_chunk(dynb + pstage * STAGEB, A, B, (c + 2) * KC, tid);
        }
        CP_COMMIT();             // commit every iteration (empty groups OK)

        uint32_t uA = dynb + stage * STAGEB + a_off;
        uint32_t uB = dynb + stage * STAGEB + MATB + b_off;
        if (++stage == NSTAGE) stage = 0;

        // Load k-step 0 fragments into buffer 0
        #pragma unroll
        for (int bp = 0; bp < 2; bp++)
            ldsm4(bF[0][bp], uB + (uint32_t)bp * 16 * ROWB);
        #pragma unroll
        for (int mt = 0; mt < 4; mt++)
            ldsm4(aF[0][mt], uA + (uint32_t)mt * 16 * ROWB);

        #pragma unroll
        for (int ks = 0; ks < 4; ks++) {
            const int cur = ks & 1;
            const int nxt = cur ^ 1;
            // Prefetch next k-step fragments BEFORE this step's MMAs:
            // their LDS latency hides under the MMA drain.
            if (ks < 3) {
                uint32_t kb = (uint32_t)(ks + 1) * 32;
                #pragma unroll
                for (int bp = 0; bp < 2; bp++)
                    ldsm4(bF[nxt][bp], uB + (uint32_t)bp * 16 * ROWB + kb);
                #pragma unroll
                for (int mt = 0; mt < 4; mt++)
                    ldsm4(aF[nxt][mt], uA + (uint32_t)mt * 16 * ROWB + kb);
            }
            // 16 independent MMAs on the current buffer
            #pragma unroll
            for (int mt = 0; mt < 4; mt++)
                #pragma unroll
                for (int nt = 0; nt < 4; nt++)
                    mma16816h(acc[mt][nt], aF[cur][mt],
                              bF[cur][nt >> 1][(nt & 1) * 2],
                              bF[cur][nt >> 1][(nt & 1) * 2 + 1]);
        }
    }

    // Epilogue in log2-domain: K = exp2(f2*d - (hi+hj)), arg clamped <= 0,
    // 4 squarings give the 5-kernel sum. hi/hj register-hoisted.
    const float LG2E = 1.4426950408889634f;
    float cs   = g_scale;
    float clg  = cs * LG2E;
    float f2   = 2.0f * clg;
    int r0 = wy * 64 + (lane >> 2);
    int c0 = wx * 32 + 2 * (lane & 3);

    float hi[8], hj[8];
    #pragma unroll
    for (int mt = 0; mt < 4; mt++) {
        hi[mt * 2]     = clg * sqa[r0 + mt * 16];
        hi[mt * 2 + 1] = clg * sqa[r0 + mt * 16 + 8];
    }
    #pragma unroll
    for (int nt = 0; nt < 4; nt++) {
        hj[nt * 2]     = clg * sqb[c0 + nt * 8];
        hj[nt * 2 + 1] = clg * sqb[c0 + nt * 8 + 1];
    }

    float psum[4] = {0.0f, 0.0f, 0.0f, 0.0f};
    #pragma unroll
    for (int mt = 0; mt < 4; mt++) {
        #pragma unroll
        for (int nt = 0; nt < 4; nt++) {
            float2 v0 = __half22float2(*(half2*)&acc[mt][nt][0]); // (r,c),(r,c+1)
            float2 v1 = __half22float2(*(half2*)&acc[mt][nt][1]); // (r+8,c),(r+8,c+1)
            float d0 = v0.x, d1 = v0.y, d2 = v1.x, d3 = v1.y;
            float a0 = fminf(fmaf(f2, d0, -(hi[mt*2]   + hj[nt*2]  )), 0.0f);
            float a1 = fminf(fmaf(f2, d1, -(hi[mt*2]   + hj[nt*2+1])), 0.0f);
            float a2 = fminf(fmaf(f2, d2, -(hi[mt*2+1] + hj[nt*2]  )), 0.0f);
            float a3 = fminf(fmaf(f2, d3, -(hi[mt*2+1] + hj[nt*2+1])), 0.0f);
            #pragma unroll
            for (int e = 0; e < 4; e++) {
                float arg = (e == 0) ? a0 : (e == 1) ? a1 : (e == 2) ? a2 : a3;
                float e1  = ex2f(arg);
                float e2  = e1 * e1;
                float e4  = e2 * e2;
                float e8  = e4 * e4;
                float e16 = e8 * e8;
                psum[mt] += ((e1 + e2) + (e4 + e8)) + e16;
            }
        }
    }
    double local = (double)((psum[0] + psum[1]) + (psum[2] + psum[3]));

    // Tile weight: sign from halves, x2 for off-diagonal (mirror tile)
    double w = ((bi < NT / 2) == (bj < NT / 2)) ? 1.0 : -1.0;
    if (bj > bi) w *= 2.0;
    local *= w;

    // Warp shfl reduce (double) + one atomic per warp
    #pragma unroll
    for (int s = 16; s > 0; s >>= 1)
        local += __shfl_xor_sync(0xFFFFFFFFu, local, s);
    if (lane == 0) {
        atomicAdd(&g_result, local);
        __threadfence();
    }

    // Fused finalize: last CTA writes the output
    __syncthreads();
    if (tid == 0) {
        unsigned int old = atomicInc(&g_pair_count, NTRI - 1);
        if (old == NTRI - 1) {
            __threadfence();
            double r = *((volatile double*)&g_result);
            out[0] = (float)(r * (1.0 / ((double)BROWS * (double)BROWS)));
        }
    }
}

// ---------------------------------------------------------------------------
extern "C" void kernel_launch(void* const* d_in, const int* in_sizes, int n_in,
                              void* d_out, int out_size) {
    const float* src = (const float*)d_in[0];
    const float* tgt = (const float*)d_in[1];
    float* out = (float*)d_out;
    (void)in_sizes; (void)n_in; (void)out_size;

    cudaFuncSetAttribute(pair10_kernel,
                         cudaFuncAttributeMaxDynamicSharedMemorySize, DYN_SMEM);

    prep_kernel<<<PREPB, 256>>>(src, tgt);
    pair10_kernel<<<NTRI, 256, DYN_SMEM>>>(out);
}

// round 11
// speedup vs baseline: 1.3263x; 1.3263x over previous
#include <cuda_runtime.h>
#include <cuda_fp16.h>
#include <cstdint>

// Problem constants
#define NROWS 8192          // n = 2*B
#define BROWS 4096          // B
#define DDIM  256           // feature dim
#define BLK   128           // tile edge
#define NT    64            // NROWS/BLK
#define NTRI  (NT*(NT+1)/2) // 2080 upper-triangular tiles
#define KC    64            // k columns per chunk (128B of fp16)
#define NCH   (DDIM/KC)     // 4 chunks per tile
#define ROWB  144           // smem row stride bytes (128B data + 16B pad)
#define MATB  (BLK*ROWB)    // 18432 B per matrix buffer
#define STAGEB (2*MATB)     // 36864 B per stage (A, B)
#define NSTAGE 3
#define DYN_SMEM (NSTAGE*STAGEB) // 110592 B
#define PREPB 256           // prep blocks

// Device scratch (no allocations allowed)
__device__ float  g_sq[NROWS];
__device__ float  g_colpart[PREPB][DDIM];
__device__ double g_s1part[PREPB];
__device__ double g_result;
__device__ float  g_scale;     // 1/(16*bandwidth)
__device__ __half g_h[NROWS * DDIM];
__device__ unsigned int g_prep_count = 0;
__device__ unsigned int g_pair_count = 0;
__device__ unsigned int g_tile_counter = 0;

// ---------------------------------------------------------------------------
__device__ __forceinline__ uint32_t smem_u32(const void* p) {
    uint32_t a;
    asm("{ .reg .u64 t; cvta.to.shared.u64 t, %1; cvt.u32.u64 %0, t; }"
        : "=r"(a) : "l"(p));
    return a;
}

__device__ __forceinline__ void ldsm4(uint32_t* r, uint32_t addr) {
    asm volatile("ldmatrix.sync.aligned.m8n8.x4.shared.b16 {%0,%1,%2,%3}, [%4];"
                 : "=r"(r[0]), "=r"(r[1]), "=r"(r[2]), "=r"(r[3]) : "r"(addr));
}

__device__ __forceinline__ void mma16816(float* c, const uint32_t* a,
                                         uint32_t b0, uint32_t b1) {
    asm volatile(
        "mma.sync.aligned.m16n8k16.row.col.f32.f16.f16.f32 "
        "{%0,%1,%2,%3}, {%4,%5,%6,%7}, {%8,%9}, {%0,%1,%2,%3};"
        : "+f"(c[0]), "+f"(c[1]), "+f"(c[2]), "+f"(c[3])
        : "r"(a[0]), "r"(a[1]), "r"(a[2]), "r"(a[3]), "r"(b0), "r"(b1));
}

__device__ __forceinline__ float ex2f(float x) {
    float r;
    asm("ex2.approx.ftz.f32 %0, %1;" : "=f"(r) : "f"(x));
    return r;
}

#define CP_ASYNC16(dst, src) \
    asm volatile("cp.async.cg.shared.global [%0], [%1], 16;" \
                 :: "r"(dst), "l"(src) : "memory")
#define CP_COMMIT() asm volatile("cp.async.commit_group;" ::: "memory")
#define CP_WAIT1()  asm volatile("cp.async.wait_group 1;" ::: "memory")

// ---------------------------------------------------------------------------
// Fused prep: row norms, per-block column partials + s1 partials, fp16 cast.
// LAST block reduces partials -> bandwidth -> g_scale, zeroes g_result and
// presets g_tile_counter = pair grid (tiles 0..grid-1 are taken implicitly).
__global__ void prep_kernel(const float* __restrict__ src,
                            const float* __restrict__ tgt,
                            unsigned int pair_grid) {
    __shared__ float  csum_s[8][DDIM];
    __shared__ double s1_s[8];
    __shared__ double red_d[256];
    __shared__ bool   is_last;

    int tid  = threadIdx.x;
    int lane = tid & 31;
    int w    = tid >> 5;
    int b    = blockIdx.x;

    float csum[8] = {0, 0, 0, 0, 0, 0, 0, 0};
    double s1 = 0.0;

    #pragma unroll
    for (int i = 0; i < 4; i++) {
        int r = b * 32 + w * 4 + i;
        const float2* row = (const float2*)((r < BROWS)
                            ? (src + (size_t)r * DDIM)
                            : (tgt + (size_t)(r - BROWS) * DDIM));
        float sq = 0.0f;
        #pragma unroll
        for (int k = 0; k < 4; k++) {
            int idx = lane + 32 * k;            // float2 index 0..127
            float2 x = row[idx];
            sq = fmaf(x.x, x.x, sq);
            sq = fmaf(x.y, x.y, sq);
            csum[2 * k]     += x.x;
            csum[2 * k + 1] += x.y;
            ((half2*)(g_h + (size_t)r * DDIM))[idx] = __floats2half2_rn(x.x, x.y);
        }
        #pragma unroll
        for (int s = 16; s > 0; s >>= 1) sq += __shfl_xor_sync(0xFFFFFFFFu, sq, s);
        if (lane == 0) { g_sq[r] = sq; s1 += (double)sq; }
    }

    #pragma unroll
    for (int k = 0; k < 4; k++) {
        csum_s[w][64 * k + 2 * lane]     = csum[2 * k];
        csum_s[w][64 * k + 2 * lane + 1] = csum[2 * k + 1];
    }
    if (lane == 0) s1_s[w] = s1;
    __syncthreads();

    float t = 0.0f;
    #pragma unroll
    for (int w2 = 0; w2 < 8; w2++) t += csum_s[w2][tid];
    g_colpart[b][tid] = t;
    if (tid == 0) {
        double bs1 = 0.0;
        #pragma unroll
        for (int w2 = 0; w2 < 8; w2++) bs1 += s1_s[w2];
        g_s1part[b] = bs1;
    }

    __threadfence();
    __syncthreads();
    if (tid == 0) {
        unsigned int old = atomicInc(&g_prep_count, PREPB - 1);
        is_last = (old == PREPB - 1);
    }
    __syncthreads();
    if (!is_last) return;
    __threadfence();

    float cs = 0.0f;
    for (int b2 = 0; b2 < PREPB; b2++) cs += g_colpart[b2][tid];
    double ssq = (double)cs * (double)cs;
    double s1v = g_s1part[tid];

    red_d[tid] = ssq;
    __syncthreads();
    #pragma unroll
    for (int s = 128; s > 0; s >>= 1) {
        if (tid < s) red_d[tid] += red_d[tid + s];
        __syncthreads();
    }
    double ss = red_d[0];
    __syncthreads();
    red_d[tid] = s1v;
    __syncthreads();
    #pragma unroll
    for (int s = 128; s > 0; s >>= 1) {
        if (tid < s) red_d[tid] += red_d[tid + s];
        __syncthreads();
    }
    if (tid == 0) {
        double S1 = red_d[0];
        const double n = (double)NROWS;
        double sum_l2 = 2.0 * n * S1 - 2.0 * ss;
        double bw = sum_l2 / (n * n - n) / 4.0;   // / KERNEL_MUL^(KERNEL_NUM/2)
        g_scale = (float)(1.0 / (bw * 16.0));     // largest sigma = bw*2^4
        g_result = 0.0;
        g_tile_counter = pair_grid;               // tiles < grid taken implicitly
    }
}

// ---------------------------------------------------------------------------
// Issue 8 cp.async (16B) per thread: one KC=64 chunk of A and B fp16 tiles.
__device__ __forceinline__ void prefetch_chunk(
    uint32_t sbase, const __half* A, const __half* B, int k0, int tid) {
    #pragma unroll
    for (int l = 0; l < 4; l++) {
        int f   = tid + l * 256;      // 0..1023
        int r   = f >> 3;             // row 0..127
        int c16 = f & 7;              // 16B group within 128B row
        uint32_t so = (uint32_t)r * ROWB + (uint32_t)c16 * 16;
        size_t  go = (size_t)r * DDIM + k0 + c16 * 8;
        CP_ASYNC16(sbase + so,        (const void*)(A + go));
        CP_ASYNC16(sbase + MATB + so, (const void*)(B + go));
    }
}

__device__ __forceinline__ void decode_tile(int t, int& bi, int& bj) {
    bi = (int)((2.0f * NT + 1.0f
          - sqrtf((float)((2 * NT + 1) * (2 * NT + 1) - 8 * t))) * 0.5f);
    while (bi * NT - bi * (bi - 1) / 2 > t) bi--;
    while ((bi + 1) * NT - (bi + 1) * bi / 2 <= t) bi++;
    bj = bi + t - (bi * NT - bi * (bi - 1) / 2);
}

// ---------------------------------------------------------------------------
// Persistent HMMA pair kernel: work-stealing tiles, f32-acc fp16 mma.sync,
// 3-stage cp.async ring that never drains across tiles (next tile's chunks
// prefetched under the current tile's tail + epilogue).
__global__ void __launch_bounds__(256, 2)
pair11_kernel(float* __restrict__ out, unsigned int pair_grid) {
    extern __shared__ __align__(16) char dyn[];
    __shared__ float sqa[2][BLK];
    __shared__ float sqb[2][BLK];
    __shared__ unsigned int s_nxt;

    int tid  = threadIdx.x;
    int lane = tid & 31;
    int wid  = tid >> 5;
    int wy   = wid >> 2;      // 0..1
    int wx   = wid & 3;       // 0..3

    uint32_t dynb = smem_u32(dyn);

    // Per-lane ldmatrix offsets (bytes) within a matrix buffer
    uint32_t a_off = (uint32_t)(wy * 64 + (lane & 15)) * ROWB + ((lane >> 4) << 4);
    uint32_t b_off = (uint32_t)(wx * 32 + (lane & 7) + ((lane >> 4) << 3)) * ROWB
                   + (((lane >> 3) & 1) << 4);

    // First tile: implicit grab = blockIdx.x
    int cur = blockIdx.x;
    int biC, bjC;
    decode_tile(cur, biC, bjC);
    const __half* Ac = g_h + (size_t)biC * BLK * DDIM;
    const __half* Bc = g_h + (size_t)bjC * BLK * DDIM;

    prefetch_chunk(dynb + 0 * STAGEB, Ac, Bc, 0, tid);
    CP_COMMIT();
    prefetch_chunk(dynb + 1 * STAGEB, Ac, Bc, KC, tid);
    CP_COMMIT();

    int buf = 0;
    if (tid < BLK) {
        sqa[0][tid] = g_sq[biC * BLK + tid];
        sqb[0][tid] = g_sq[bjC * BLK + tid];
    }

    const float LG2E = 1.4426950408889634f;
    float clg = g_scale * LG2E;
    float f2  = 2.0f * clg;
    int r0 = wy * 64 + (lane >> 2);
    int c0 = wx * 32 + 2 * (lane & 3);

    int stage = 0;
    for (;;) {
        // Grab next tile (thread 0), broadcast
        if (tid == 0) s_nxt = atomicAdd(&g_tile_counter, 1u);
        __syncthreads();
        int nxt = (int)s_nxt;
        bool has_nxt = (nxt < NTRI);
        int biN = 0, bjN = 0;
        const __half *An = Ac, *Bn = Bc;
        if (has_nxt) {
            decode_tile(nxt, biN, bjN);
            An = g_h + (size_t)biN * BLK * DDIM;
            Bn = g_h + (size_t)bjN * BLK * DDIM;
            if (tid < BLK) {
                sqa[buf ^ 1][tid] = g_sq[biN * BLK + tid];
                sqb[buf ^ 1][tid] = g_sq[bjN * BLK + tid];
            }
        }

        float acc[4][4][4];
        #pragma unroll
        for (int mt = 0; mt < 4; mt++)
            #pragma unroll
            for (int nt = 0; nt < 4; nt++)
                #pragma unroll
                for (int e = 0; e < 4; e++) acc[mt][nt][e] = 0.0f;

        #pragma unroll
        for (int c = 0; c < NCH; c++) {
            CP_WAIT1();              // chunk c of cur complete
            __syncthreads();         // visible to all; ring slot c-1 free
            if (c < 2) {
                int ps = stage + 2; if (ps >= NSTAGE) ps -= NSTAGE;
                prefetch_chunk(dynb + ps * STAGEB, Ac, Bc, (c + 2) * KC, tid);
            } else if (has_nxt) {
                int ps = stage + 2; if (ps >= NSTAGE) ps -= NSTAGE;
                prefetch_chunk(dynb + ps * STAGEB, An, Bn, (c - 2) * KC, tid);
            }
            CP_COMMIT();             // one group per chunk (possibly empty)

            uint32_t uA = dynb + stage * STAGEB + a_off;
            uint32_t uB = dynb + stage * STAGEB + MATB + b_off;
            if (++stage == NSTAGE) stage = 0;

            #pragma unroll
            for (int ks = 0; ks < 4; ks++) {
                uint32_t kb = (uint32_t)ks * 32;    // 16 fp16 = 32 bytes
                uint32_t bf[2][4];
                #pragma unroll
                for (int bp = 0; bp < 2; bp++)
                    ldsm4(bf[bp], uB + (uint32_t)bp * 16 * ROWB + kb);
                uint32_t a[4][4];
                #pragma unroll
                for (int mt = 0; mt < 4; mt++)
                    ldsm4(a[mt], uA + (uint32_t)mt * 16 * ROWB + kb);
                #pragma unroll
                for (int mt = 0; mt < 4; mt++)
                    #pragma unroll
                    for (int nt = 0; nt < 4; nt++)
                        mma16816(acc[mt][nt], a[mt],
                                 bf[nt >> 1][(nt & 1) * 2],
                                 bf[nt >> 1][(nt & 1) * 2 + 1]);
            }
        }

        // Epilogue (runs while next tile's chunks stream in)
        float hi[8], hj[8];
        #pragma unroll
        for (int mt = 0; mt < 4; mt++) {
            hi[mt * 2]     = clg * sqa[buf][r0 + mt * 16];
            hi[mt * 2 + 1] = clg * sqa[buf][r0 + mt * 16 + 8];
        }
        #pragma unroll
        for (int nt = 0; nt < 4; nt++) {
            hj[nt * 2]     = clg * sqb[buf][c0 + nt * 8];
            hj[nt * 2 + 1] = clg * sqb[buf][c0 + nt * 8 + 1];
        }

        float psum[4] = {0.0f, 0.0f, 0.0f, 0.0f};
        #pragma unroll
        for (int mt = 0; mt < 4; mt++) {
            #pragma unroll
            for (int nt = 0; nt < 4; nt++) {
                #pragma unroll
                for (int e = 0; e < 4; e++) {
                    float d   = acc[mt][nt][e];
                    float arg = fminf(fmaf(f2, d,
                                      -(hi[mt * 2 + (e >> 1)] + hj[nt * 2 + (e & 1)])),
                                      0.0f);
                    float e1  = ex2f(arg);
                    float e2  = e1 * e1;
                    float e4  = e2 * e2;
                    float e8  = e4 * e4;
                    float e16 = e8 * e8;
                    psum[mt] += ((e1 + e2) + (e4 + e8)) + e16;
                }
            }
        }
        double local = (double)((psum[0] + psum[1]) + (psum[2] + psum[3]));

        double w = ((biC < NT / 2) == (bjC < NT / 2)) ? 1.0 : -1.0;
        if (bjC > biC) w *= 2.0;
        local *= w;

        #pragma unroll
        for (int s = 16; s > 0; s >>= 1)
            local += __shfl_xor_sync(0xFFFFFFFFu, local, s);
        if (lane == 0) atomicAdd(&g_result, local);

        if (!has_nxt) break;
        cur = nxt; biC = biN; bjC = bjN; Ac = An; Bc = Bn; buf ^= 1;
    }

    // Fused finalize: last CTA to finish writes the output
    if (lane == 0) __threadfence();
    __syncthreads();
    if (tid == 0) {
        unsigned int old = atomicInc(&g_pair_count, pair_grid - 1);
        if (old == pair_grid - 1) {
            __threadfence();
            double r = *((volatile double*)&g_result);
            out[0] = (float)(r * (1.0 / ((double)BROWS * (double)BROWS)));
        }
    }
}

// ---------------------------------------------------------------------------
extern "C" void kernel_launch(void* const* d_in, const int* in_sizes, int n_in,
                              void* d_out, int out_size) {
    const float* src = (const float*)d_in[0];
    const float* tgt = (const float*)d_in[1];
    float* out = (float*)d_out;
    (void)in_sizes; (void)n_in; (void)out_size;

    cudaFuncSetAttribute(pair11_kernel,
                         cudaFuncAttributeMaxDynamicSharedMemorySize, DYN_SMEM);

    int dev = 0, nsm = 148;
    cudaGetDevice(&dev);
    cudaDeviceGetAttribute(&nsm, cudaDevAttrMultiProcessorCount, dev);
    unsigned int pair_grid = (unsigned int)(2 * nsm);

    prep_kernel<<<PREPB, 256>>>(src, tgt, pair_grid);
    pair11_kernel<<<pair_grid, 256, DYN_SMEM>>>(out, pair_grid);
}

// round 12
// speedup vs baseline: 1.4058x; 1.0599x over previous
#include <cuda_runtime.h>
#include <cuda_fp16.h>
#include <cstdint>

// Problem constants
#define NROWS 8192          // n = 2*B
#define BROWS 4096          // B
#define DDIM  256           // feature dim
#define BLK   128           // tile edge
#define NT    64            // NROWS/BLK
#define NTRI  (NT*(NT+1)/2) // 2080 upper-triangular tiles
#define KC    64            // k columns per chunk (128B of fp16)
#define NCH   (DDIM/KC)     // 4 chunks per tile
#define ROWB  144           // smem row stride bytes (128B data + 16B pad)
#define MATB  (BLK*ROWB)    // 18432 B per matrix buffer
#define STAGEB (2*MATB)     // 36864 B per stage (A, B)
#define NSTAGE 3
#define DYN_SMEM (NSTAGE*STAGEB) // 110592 B
#define PREPB 256           // prep blocks

// Device scratch (no allocations allowed)
__device__ float  g_sq[NROWS];
__device__ float  g_colpart[PREPB][DDIM];
__device__ double g_s1part[PREPB];
__device__ double g_result;
__device__ float  g_scale;     // 1/(16*bandwidth)
__device__ __half g_h[NROWS * DDIM];
__device__ unsigned int g_prep_count = 0;
__device__ unsigned int g_pair_count = 0;
__device__ unsigned int g_tile_counter = 0;

// ---------------------------------------------------------------------------
__device__ __forceinline__ uint32_t smem_u32(const void* p) {
    uint32_t a;
    asm("{ .reg .u64 t; cvta.to.shared.u64 t, %1; cvt.u32.u64 %0, t; }"
        : "=r"(a) : "l"(p));
    return a;
}

__device__ __forceinline__ void ldsm4(uint32_t* r, uint32_t addr) {
    asm volatile("ldmatrix.sync.aligned.m8n8.x4.shared.b16 {%0,%1,%2,%3}, [%4];"
                 : "=r"(r[0]), "=r"(r[1]), "=r"(r[2]), "=r"(r[3]) : "r"(addr));
}

__device__ __forceinline__ void mma16816(float* c, const uint32_t* a,
                                         uint32_t b0, uint32_t b1) {
    asm volatile(
        "mma.sync.aligned.m16n8k16.row.col.f32.f16.f16.f32 "
        "{%0,%1,%2,%3}, {%4,%5,%6,%7}, {%8,%9}, {%0,%1,%2,%3};"
        : "+f"(c[0]), "+f"(c[1]), "+f"(c[2]), "+f"(c[3])
        : "r"(a[0]), "r"(a[1]), "r"(a[2]), "r"(a[3]), "r"(b0), "r"(b1));
}

__device__ __forceinline__ float ex2f(float x) {
    float r;
    asm("ex2.approx.ftz.f32 %0, %1;" : "=f"(r) : "f"(x));
    return r;
}

#define CP_ASYNC16(dst, src) \
    asm volatile("cp.async.cg.shared.global [%0], [%1], 16;" \
                 :: "r"(dst), "l"(src) : "memory")
#define CP_COMMIT() asm volatile("cp.async.commit_group;" ::: "memory")
#define CP_WAIT1()  asm volatile("cp.async.wait_group 1;" ::: "memory")

// ---------------------------------------------------------------------------
// Fused prep: row norms, per-block column partials + s1 partials, fp16 cast.
// LAST block reduces partials -> bandwidth -> g_scale, zeroes g_result and
// presets g_tile_counter = pair grid (tiles 0..grid-1 are taken implicitly).
__global__ void prep_kernel(const float* __restrict__ src,
                            const float* __restrict__ tgt,
                            unsigned int pair_grid) {
    __shared__ float  csum_s[8][DDIM];
    __shared__ double s1_s[8];
    __shared__ double red_d[256];
    __shared__ bool   is_last;

    int tid  = threadIdx.x;
    int lane = tid & 31;
    int w    = tid >> 5;
    int b    = blockIdx.x;

    float csum[8] = {0, 0, 0, 0, 0, 0, 0, 0};
    double s1 = 0.0;

    #pragma unroll
    for (int i = 0; i < 4; i++) {
        int r = b * 32 + w * 4 + i;
        const float2* row = (const float2*)((r < BROWS)
                            ? (src + (size_t)r * DDIM)
                            : (tgt + (size_t)(r - BROWS) * DDIM));
        float sq = 0.0f;
        #pragma unroll
        for (int k = 0; k < 4; k++) {
            int idx = lane + 32 * k;            // float2 index 0..127
            float2 x = row[idx];
            sq = fmaf(x.x, x.x, sq);
            sq = fmaf(x.y, x.y, sq);
            csum[2 * k]     += x.x;
            csum[2 * k + 1] += x.y;
            ((half2*)(g_h + (size_t)r * DDIM))[idx] = __floats2half2_rn(x.x, x.y);
        }
        #pragma unroll
        for (int s = 16; s > 0; s >>= 1) sq += __shfl_xor_sync(0xFFFFFFFFu, sq, s);
        if (lane == 0) { g_sq[r] = sq; s1 += (double)sq; }
    }

    #pragma unroll
    for (int k = 0; k < 4; k++) {
        csum_s[w][64 * k + 2 * lane]     = csum[2 * k];
        csum_s[w][64 * k + 2 * lane + 1] = csum[2 * k + 1];
    }
    if (lane == 0) s1_s[w] = s1;
    __syncthreads();

    float t = 0.0f;
    #pragma unroll
    for (int w2 = 0; w2 < 8; w2++) t += csum_s[w2][tid];
    g_colpart[b][tid] = t;
    if (tid == 0) {
        double bs1 = 0.0;
        #pragma unroll
        for (int w2 = 0; w2 < 8; w2++) bs1 += s1_s[w2];
        g_s1part[b] = bs1;
    }

    __threadfence();
    __syncthreads();
    if (tid == 0) {
        unsigned int old = atomicInc(&g_prep_count, PREPB - 1);
        is_last = (old == PREPB - 1);
    }
    __syncthreads();
    if (!is_last) return;
    __threadfence();

    float cs = 0.0f;
    for (int b2 = 0; b2 < PREPB; b2++) cs += g_colpart[b2][tid];
    double ssq = (double)cs * (double)cs;
    double s1v = g_s1part[tid];

    red_d[tid] = ssq;
    __syncthreads();
    #pragma unroll
    for (int s = 128; s > 0; s >>= 1) {
        if (tid < s) red_d[tid] += red_d[tid + s];
        __syncthreads();
    }
    double ss = red_d[0];
    __syncthreads();
    red_d[tid] = s1v;
    __syncthreads();
    #pragma unroll
    for (int s = 128; s > 0; s >>= 1) {
        if (tid < s) red_d[tid] += red_d[tid + s];
        __syncthreads();
    }
    if (tid == 0) {
        double S1 = red_d[0];
        const double n = (double)NROWS;
        double sum_l2 = 2.0 * n * S1 - 2.0 * ss;
        double bw = sum_l2 / (n * n - n) / 4.0;   // / KERNEL_MUL^(KERNEL_NUM/2)
        g_scale = (float)(1.0 / (bw * 16.0));     // largest sigma = bw*2^4
        g_result = 0.0;
        g_tile_counter = pair_grid;               // tiles < grid taken implicitly
    }
}

// ---------------------------------------------------------------------------
// Issue 8 cp.async (16B) per thread: one KC=64 chunk of A and B fp16 tiles.
__device__ __forceinline__ void prefetch_chunk(
    uint32_t sbase, const __half* A, const __half* B, int k0, int tid) {
    #pragma unroll
    for (int l = 0; l < 4; l++) {
        int f   = tid + l * 256;      // 0..1023
        int r   = f >> 3;             // row 0..127
        int c16 = f & 7;              // 16B group within 128B row
        uint32_t so = (uint32_t)r * ROWB + (uint32_t)c16 * 16;
        size_t  go = (size_t)r * DDIM + k0 + c16 * 8;
        CP_ASYNC16(sbase + so,        (const void*)(A + go));
        CP_ASYNC16(sbase + MATB + so, (const void*)(B + go));
    }
}

__device__ __forceinline__ void decode_tile(int t, int& bi, int& bj) {
    bi = (int)((2.0f * NT + 1.0f
          - sqrtf((float)((2 * NT + 1) * (2 * NT + 1) - 8 * t))) * 0.5f);
    while (bi * NT - bi * (bi - 1) / 2 > t) bi--;
    while ((bi + 1) * NT - (bi + 1) * bi / 2 <= t) bi++;
    bj = bi + t - (bi * NT - bi * (bi - 1) / 2);
}

// ---------------------------------------------------------------------------
// Persistent HMMA pair kernel: work-stealing with EARLY tile grab (atomic
// hidden under chunk-0 compute), f32-acc fp16 mma.sync, A-fragment double
// buffering (LDSM latency hidden under tensor drain), 3-stage cp.async ring
// that never drains across tiles; fused finalize.
__global__ void __launch_bounds__(256, 2)
pair12_kernel(float* __restrict__ out, unsigned int pair_grid) {
    extern __shared__ __align__(16) char dyn[];
    __shared__ float sqa[2][BLK];
    __shared__ float sqb[2][BLK];
    __shared__ unsigned int s_nxt;

    int tid  = threadIdx.x;
    int lane = tid & 31;
    int wid  = tid >> 5;
    int wy   = wid >> 2;      // 0..1
    int wx   = wid & 3;       // 0..3

    uint32_t dynb = smem_u32(dyn);

    // Per-lane ldmatrix offsets (bytes) within a matrix buffer
    uint32_t a_off = (uint32_t)(wy * 64 + (lane & 15)) * ROWB + ((lane >> 4) << 4);
    uint32_t b_off = (uint32_t)(wx * 32 + (lane & 7) + ((lane >> 4) << 3)) * ROWB
                   + (((lane >> 3) & 1) << 4);

    // First tile: implicit grab = blockIdx.x
    int biC, bjC;
    decode_tile((int)blockIdx.x, biC, bjC);
    const __half* Ac = g_h + (size_t)biC * BLK * DDIM;
    const __half* Bc = g_h + (size_t)bjC * BLK * DDIM;

    prefetch_chunk(dynb + 0 * STAGEB, Ac, Bc, 0, tid);
    CP_COMMIT();
    prefetch_chunk(dynb + 1 * STAGEB, Ac, Bc, KC, tid);
    CP_COMMIT();

    int buf = 0;
    if (tid < BLK) {
        sqa[0][tid] = g_sq[biC * BLK + tid];
        sqb[0][tid] = g_sq[bjC * BLK + tid];
    }

    const float LG2E = 1.4426950408889634f;
    float clg = g_scale * LG2E;
    float f2  = 2.0f * clg;
    int r0 = wy * 64 + (lane >> 2);
    int c0 = wx * 32 + 2 * (lane & 3);

    int stage = 0;
    for (;;) {
        int biN = 0, bjN = 0;
        const __half *An = Ac, *Bn = Bc;
        bool has_nxt = false;
        int nxt = 0;

        float acc[4][4][4];
        #pragma unroll
        for (int mt = 0; mt < 4; mt++)
            #pragma unroll
            for (int nt = 0; nt < 4; nt++)
                #pragma unroll
                for (int e = 0; e < 4; e++) acc[mt][nt][e] = 0.0f;

        #pragma unroll
        for (int c = 0; c < NCH; c++) {
            CP_WAIT1();              // chunk c of cur complete
            __syncthreads();         // visible to all; ring slot free;
                                     // (c==1) also publishes s_nxt
            if (c == 0) {
                int ps = stage + 2; if (ps >= NSTAGE) ps -= NSTAGE;
                prefetch_chunk(dynb + ps * STAGEB, Ac, Bc, 2 * KC, tid);
                // EARLY grab: atomic latency hides under chunk-0/1 compute
                if (tid == 0) s_nxt = atomicAdd(&g_tile_counter, 1u);
            } else if (c == 1) {
                int ps = stage + 2; if (ps >= NSTAGE) ps -= NSTAGE;
                prefetch_chunk(dynb + ps * STAGEB, Ac, Bc, 3 * KC, tid);
                nxt = (int)s_nxt;
                has_nxt = (nxt < NTRI);
                if (has_nxt) {
                    decode_tile(nxt, biN, bjN);
                    An = g_h + (size_t)biN * BLK * DDIM;
                    Bn = g_h + (size_t)bjN * BLK * DDIM;
                    if (tid < BLK) {
                        sqa[buf ^ 1][tid] = g_sq[biN * BLK + tid];
                        sqb[buf ^ 1][tid] = g_sq[bjN * BLK + tid];
                    }
                }
            } else if (has_nxt) {
                int ps = stage + 2; if (ps >= NSTAGE) ps -= NSTAGE;
                prefetch_chunk(dynb + ps * STAGEB, An, Bn, (c - 2) * KC, tid);
            }
            CP_COMMIT();             // one group per chunk (possibly empty)

            uint32_t uA = dynb + stage * STAGEB + a_off;
            uint32_t uB = dynb + stage * STAGEB + MATB + b_off;
            if (++stage == NSTAGE) stage = 0;

            // Software-pipelined k-loop: A fragments double-buffered
            // (prefetched before MMAs), B reloaded after MMAs (WAR-safe).
            uint32_t aF[2][4][4];
            uint32_t bC[2][4];
            #pragma unroll
            for (int bp = 0; bp < 2; bp++)
                ldsm4(bC[bp], uB + (uint32_t)bp * 16 * ROWB);
            #pragma unroll
            for (int mt = 0; mt < 4; mt++)
                ldsm4(aF[0][mt], uA + (uint32_t)mt * 16 * ROWB);

            #pragma unroll
            for (int ks = 0; ks < 4; ks++) {
                const int cb = ks & 1;
                const int nb = cb ^ 1;
                if (ks < 3) {
                    uint32_t kb = (uint32_t)(ks + 1) * 32;
                    #pragma unroll
                    for (int mt = 0; mt < 4; mt++)
                        ldsm4(aF[nb][mt], uA + (uint32_t)mt * 16 * ROWB + kb);
                }
                #pragma unroll
                for (int mt = 0; mt < 4; mt++)
                    #pragma unroll
                    for (int nt = 0; nt < 4; nt++)
                        mma16816(acc[mt][nt], aF[cb][mt],
                                 bC[nt >> 1][(nt & 1) * 2],
                                 bC[nt >> 1][(nt & 1) * 2 + 1]);
                if (ks < 3) {
                    uint32_t kb = (uint32_t)(ks + 1) * 32;
                    #pragma unroll
                    for (int bp = 0; bp < 2; bp++)
                        ldsm4(bC[bp], uB + (uint32_t)bp * 16 * ROWB + kb);
                }
            }
        }

        // Epilogue (runs while next tile's chunks stream in)
        float hi[8], hj[8];
        #pragma unroll
        for (int mt = 0; mt < 4; mt++) {
            hi[mt * 2]     = clg * sqa[buf][r0 + mt * 16];
            hi[mt * 2 + 1] = clg * sqa[buf][r0 + mt * 16 + 8];
        }
        #pragma unroll
        for (int nt = 0; nt < 4; nt++) {
            hj[nt * 2]     = clg * sqb[buf][c0 + nt * 8];
            hj[nt * 2 + 1] = clg * sqb[buf][c0 + nt * 8 + 1];
        }

        float psum[4] = {0.0f, 0.0f, 0.0f, 0.0f};
        #pragma unroll
        for (int mt = 0; mt < 4; mt++) {
            #pragma unroll
            for (int nt = 0; nt < 4; nt++) {
                #pragma unroll
                for (int e = 0; e < 4; e++) {
                    float d   = acc[mt][nt][e];
                    float arg = fminf(fmaf(f2, d,
                                      -(hi[mt * 2 + (e >> 1)] + hj[nt * 2 + (e & 1)])),
                                      0.0f);
                    float e1  = ex2f(arg);
                    float e2  = e1 * e1;
                    float e4  = e2 * e2;
                    float e8  = e4 * e4;
                    float e16 = e8 * e8;
                    psum[mt] += ((e1 + e2) + (e4 + e8)) + e16;
                }
            }
        }
        double local = (double)((psum[0] + psum[1]) + (psum[2] + psum[3]));

        double w = ((biC < NT / 2) == (bjC < NT / 2)) ? 1.0 : -1.0;
        if (bjC > biC) w *= 2.0;
        local *= w;

        #pragma unroll
        for (int s = 16; s > 0; s >>= 1)
            local += __shfl_xor_sync(0xFFFFFFFFu, local, s);
        if (lane == 0) atomicAdd(&g_result, local);

        if (!has_nxt) break;
        biC = biN; bjC = bjN; Ac = An; Bc = Bn; buf ^= 1;
    }

    // Fused finalize: last CTA to finish writes the output
    if (lane == 0) __threadfence();
    __syncthreads();
    if (tid == 0) {
        unsigned int old = atomicInc(&g_pair_count, pair_grid - 1);
        if (old == pair_grid - 1) {
            __threadfence();
            double r = *((volatile double*)&g_result);
            out[0] = (float)(r * (1.0 / ((double)BROWS * (double)BROWS)));
        }
    }
}

// ---------------------------------------------------------------------------
extern "C" void kernel_launch(void* const* d_in, const int* in_sizes, int n_in,
                              void* d_out, int out_size) {
    const float* src = (const float*)d_in[0];
    const float* tgt = (const float*)d_in[1];
    float* out = (float*)d_out;
    (void)in_sizes; (void)n_in; (void)out_size;

    cudaFuncSetAttribute(pair12_kernel,
                         cudaFuncAttributeMaxDynamicSharedMemorySize, DYN_SMEM);

    int dev = 0, nsm = 148;
    cudaGetDevice(&dev);
    cudaDeviceGetAttribute(&nsm, cudaDevAttrMultiProcessorCount, dev);
    unsigned int pair_grid = (unsigned int)(2 * nsm);

    prep_kernel<<<PREPB, 256>>>(src, tgt, pair_grid);
    pair12_kernel<<<pair_grid, 256, DYN_SMEM>>>(out, pair_grid);
}

// round 13
// speedup vs baseline: 1.4477x; 1.0298x over previous
#include <cuda_runtime.h>
#include <cuda_fp16.h>
#include <cstdint>

// Problem constants
#define NROWS 8192          // n = 2*B
#define BROWS 4096          // B
#define DDIM  256           // feature dim
#define BLK   128           // tile edge
#define NT    64            // NROWS/BLK
#define NTRI  (NT*(NT+1)/2) // 2080 upper-triangular tiles
#define KC    64            // k columns per chunk (128B of fp16)
#define NCH   (DDIM/KC)     // 4 chunks per tile
#define ROWB  144           // smem row stride bytes (128B data + 16B pad)
#define MATB  (BLK*ROWB)    // 18432 B per matrix buffer
#define STAGEB (2*MATB)     // 36864 B per stage (A, B)
#define NSTAGE 3
#define DYN_SMEM (NSTAGE*STAGEB) // 110592 B
#define PREPB 256           // prep blocks
#define STAGGER_CYC 3500ULL // anti-phase offset for 2nd co-resident CTA

// Device scratch (no allocations allowed)
__device__ float  g_sq[NROWS];
__device__ float  g_colpart[PREPB][DDIM];
__device__ double g_s1part[PREPB];
__device__ double g_result;
__device__ float  g_scale;     // 1/(16*bandwidth)
__device__ __half g_h[NROWS * DDIM];
__device__ unsigned int g_prep_count = 0;
__device__ unsigned int g_pair_count = 0;

// ---------------------------------------------------------------------------
__device__ __forceinline__ uint32_t smem_u32(const void* p) {
    uint32_t a;
    asm("{ .reg .u64 t; cvta.to.shared.u64 t, %1; cvt.u32.u64 %0, t; }"
        : "=r"(a) : "l"(p));
    return a;
}

__device__ __forceinline__ void ldsm4(uint32_t* r, uint32_t addr) {
    asm volatile("ldmatrix.sync.aligned.m8n8.x4.shared.b16 {%0,%1,%2,%3}, [%4];"
                 : "=r"(r[0]), "=r"(r[1]), "=r"(r[2]), "=r"(r[3]) : "r"(addr));
}

__device__ __forceinline__ void mma16816(float* c, const uint32_t* a,
                                         uint32_t b0, uint32_t b1) {
    asm volatile(
        "mma.sync.aligned.m16n8k16.row.col.f32.f16.f16.f32 "
        "{%0,%1,%2,%3}, {%4,%5,%6,%7}, {%8,%9}, {%0,%1,%2,%3};"
        : "+f"(c[0]), "+f"(c[1]), "+f"(c[2]), "+f"(c[3])
        : "r"(a[0]), "r"(a[1]), "r"(a[2]), "r"(a[3]), "r"(b0), "r"(b1));
}

__device__ __forceinline__ float ex2f(float x) {
    float r;
    asm("ex2.approx.ftz.f32 %0, %1;" : "=f"(r) : "f"(x));
    return r;
}

#define CP_ASYNC16(dst, src) \
    asm volatile("cp.async.cg.shared.global [%0], [%1], 16;" \
                 :: "r"(dst), "l"(src) : "memory")
#define CP_COMMIT() asm volatile("cp.async.commit_group;" ::: "memory")
#define CP_WAIT1()  asm volatile("cp.async.wait_group 1;" ::: "memory")

// ---------------------------------------------------------------------------
// Fused prep: row norms, per-block column partials + s1 partials, fp16 cast.
// LAST block reduces partials -> bandwidth -> g_scale, zeroes g_result.
__global__ void prep_kernel(const float* __restrict__ src,
                            const float* __restrict__ tgt) {
    __shared__ float  csum_s[8][DDIM];
    __shared__ double s1_s[8];
    __shared__ double red_d[256];
    __shared__ bool   is_last;

    int tid  = threadIdx.x;
    int lane = tid & 31;
    int w    = tid >> 5;
    int b    = blockIdx.x;

    float csum[8] = {0, 0, 0, 0, 0, 0, 0, 0};
    double s1 = 0.0;

    #pragma unroll
    for (int i = 0; i < 4; i++) {
        int r = b * 32 + w * 4 + i;
        const float2* row = (const float2*)((r < BROWS)
                            ? (src + (size_t)r * DDIM)
                            : (tgt + (size_t)(r - BROWS) * DDIM));
        float sq = 0.0f;
        #pragma unroll
        for (int k = 0; k < 4; k++) {
            int idx = lane + 32 * k;            // float2 index 0..127
            float2 x = row[idx];
            sq = fmaf(x.x, x.x, sq);
            sq = fmaf(x.y, x.y, sq);
            csum[2 * k]     += x.x;
            csum[2 * k + 1] += x.y;
            ((half2*)(g_h + (size_t)r * DDIM))[idx] = __floats2half2_rn(x.x, x.y);
        }
        #pragma unroll
        for (int s = 16; s > 0; s >>= 1) sq += __shfl_xor_sync(0xFFFFFFFFu, sq, s);
        if (lane == 0) { g_sq[r] = sq; s1 += (double)sq; }
    }

    #pragma unroll
    for (int k = 0; k < 4; k++) {
        csum_s[w][64 * k + 2 * lane]     = csum[2 * k];
        csum_s[w][64 * k + 2 * lane + 1] = csum[2 * k + 1];
    }
    if (lane == 0) s1_s[w] = s1;
    __syncthreads();

    float t = 0.0f;
    #pragma unroll
    for (int w2 = 0; w2 < 8; w2++) t += csum_s[w2][tid];
    g_colpart[b][tid] = t;
    if (tid == 0) {
        double bs1 = 0.0;
        #pragma unroll
        for (int w2 = 0; w2 < 8; w2++) bs1 += s1_s[w2];
        g_s1part[b] = bs1;
    }

    __threadfence();
    __syncthreads();
    if (tid == 0) {
        unsigned int old = atomicInc(&g_prep_count, PREPB - 1);
        is_last = (old == PREPB - 1);
    }
    __syncthreads();
    if (!is_last) return;
    __threadfence();

    float cs = 0.0f;
    for (int b2 = 0; b2 < PREPB; b2++) cs += g_colpart[b2][tid];
    double ssq = (double)cs * (double)cs;
    double s1v = g_s1part[tid];

    red_d[tid] = ssq;
    __syncthreads();
    #pragma unroll
    for (int s = 128; s > 0; s >>= 1) {
        if (tid < s) red_d[tid] += red_d[tid + s];
        __syncthreads();
    }
    double ss = red_d[0];
    __syncthreads();
    red_d[tid] = s1v;
    __syncthreads();
    #pragma unroll
    for (int s = 128; s > 0; s >>= 1) {
        if (tid < s) red_d[tid] += red_d[tid + s];
        __syncthreads();
    }
    if (tid == 0) {
        double S1 = red_d[0];
        const double n = (double)NROWS;
        double sum_l2 = 2.0 * n * S1 - 2.0 * ss;
        double bw = sum_l2 / (n * n - n) / 4.0;   // / KERNEL_MUL^(KERNEL_NUM/2)
        g_scale = (float)(1.0 / (bw * 16.0));     // largest sigma = bw*2^4
        g_result = 0.0;
    }
}

// ---------------------------------------------------------------------------
// Issue 8 cp.async (16B) per thread: one KC=64 chunk of A and B fp16 tiles.
__device__ __forceinline__ void prefetch_chunk(
    uint32_t sbase, const __half* A, const __half* B, int k0, int tid) {
    #pragma unroll
    for (int l = 0; l < 4; l++) {
        int f   = tid + l * 256;      // 0..1023
        int r   = f >> 3;             // row 0..127
        int c16 = f & 7;              // 16B group within 128B row
        uint32_t so = (uint32_t)r * ROWB + (uint32_t)c16 * 16;
        size_t  go = (size_t)r * DDIM + k0 + c16 * 8;
        CP_ASYNC16(sbase + so,        (const void*)(A + go));
        CP_ASYNC16(sbase + MATB + so, (const void*)(B + go));
    }
}

// ---------------------------------------------------------------------------
// HMMA pair kernel (r9 skeleton): one 128x128 tile per CTA, f32-acc fp16
// mma.sync, 3-stage cp.async ring, pipelined k-loop. NEW: anti-phase stagger
// for the second co-resident CTA slot so its epilogue (fma/mufu-bound) runs
// under the partner CTA's mainloop (tensor-bound) instead of colliding.
__global__ void __launch_bounds__(256, 2)
pair13_kernel(float* __restrict__ out, int nsm) {
    extern __shared__ __align__(16) char dyn[];
    __shared__ float sqa[BLK];
    __shared__ float sqb[BLK];

    int tid  = threadIdx.x;
    int lane = tid & 31;
    int wid  = tid >> 5;
    int wy   = wid >> 2;      // 0..1
    int wx   = wid & 3;       // 0..3

    // Closed-form triangular decode: bi = row of tile, bj >= bi
    int rem = blockIdx.x;
    int bi = (int)((2.0f * NT + 1.0f
              - sqrtf((float)((2 * NT + 1) * (2 * NT + 1) - 8 * rem))) * 0.5f);
    while (bi * NT - bi * (bi - 1) / 2 > rem) bi--;
    while ((bi + 1) * NT - (bi + 1) * bi / 2 <= rem) bi++;
    int bj = bi + rem - (bi * NT - bi * (bi - 1) / 2);

    const __half* A = g_h + (size_t)bi * BLK * DDIM;
    const __half* B = g_h + (size_t)bj * BLK * DDIM;

    uint32_t dynb = smem_u32(dyn);

    // Prologue: 2 chunks in flight (issued BEFORE the stagger spin, so the
    // delayed CTA's loads stream in during its spin)
    prefetch_chunk(dynb + 0 * STAGEB, A, B, 0, tid);
    CP_COMMIT();
    prefetch_chunk(dynb + 1 * STAGEB, A, B, KC, tid);
    CP_COMMIT();

    // Anti-phase stagger: CTAs in the second SM slot (first wave) start half
    // a tile-period late; successor CTAs inherit the slot phase.
    if (blockIdx.x >= (unsigned)nsm && blockIdx.x < (unsigned)(2 * nsm)) {
        unsigned long long t0 = clock64();
        while (clock64() - t0 < STAGGER_CYC) { }
    }

    if (tid < BLK) {
        sqa[tid] = g_sq[bi * BLK + tid];
        sqb[tid] = g_sq[bj * BLK + tid];
    }

    float acc[4][4][4];
    #pragma unroll
    for (int mt = 0; mt < 4; mt++)
        #pragma unroll
        for (int nt = 0; nt < 4; nt++)
            #pragma unroll
            for (int e = 0; e < 4; e++) acc[mt][nt][e] = 0.0f;

    // Per-lane ldmatrix offsets (bytes) within a matrix buffer
    uint32_t a_off = (uint32_t)(wy * 64 + (lane & 15)) * ROWB + ((lane >> 4) << 4);
    uint32_t b_off = (uint32_t)(wx * 32 + (lane & 7) + ((lane >> 4) << 3)) * ROWB
                   + (((lane >> 3) & 1) << 4);

    int stage = 0;
    #pragma unroll
    for (int c = 0; c < NCH; c++) {
        CP_WAIT1();              // chunk c complete (<=1 younger group pending)
        __syncthreads();         // chunk c visible to all; stage c+2 free
        if (c + 2 < NCH) {
            int ps = stage + 2; if (ps >= NSTAGE) ps -= NSTAGE;
            prefetch_chunk(dynb + ps * STAGEB, A, B, (c + 2) * KC, tid);
        }
        CP_COMMIT();             // one group per chunk (possibly empty)

        uint32_t uA = dynb + stage * STAGEB + a_off;
        uint32_t uB = dynb + stage * STAGEB + MATB + b_off;
        if (++stage == NSTAGE) stage = 0;

        // Software-pipelined k-loop: A fragments double-buffered (prefetched
        // before the MMAs), B reloaded after the MMAs (WAR-safe; latency
        // hidden under the tensor drain).
        uint32_t aF[2][4][4];
        uint32_t bC[2][4];
        #pragma unroll
        for (int bp = 0; bp < 2; bp++)
            ldsm4(bC[bp], uB + (uint32_t)bp * 16 * ROWB);
        #pragma unroll
        for (int mt = 0; mt < 4; mt++)
            ldsm4(aF[0][mt], uA + (uint32_t)mt * 16 * ROWB);

        #pragma unroll
        for (int ks = 0; ks < 4; ks++) {
            const int cb = ks & 1;
            const int nb = cb ^ 1;
            if (ks < 3) {
                uint32_t kb = (uint32_t)(ks + 1) * 32;
                #pragma unroll
                for (int mt = 0; mt < 4; mt++)
                    ldsm4(aF[nb][mt], uA + (uint32_t)mt * 16 * ROWB + kb);
            }
            #pragma unroll
            for (int mt = 0; mt < 4; mt++)
                #pragma unroll
                for (int nt = 0; nt < 4; nt++)
                    mma16816(acc[mt][nt], aF[cb][mt],
                             bC[nt >> 1][(nt & 1) * 2],
                             bC[nt >> 1][(nt & 1) * 2 + 1]);
            if (ks < 3) {
                uint32_t kb = (uint32_t)(ks + 1) * 32;
                #pragma unroll
                for (int bp = 0; bp < 2; bp++)
                    ldsm4(bC[bp], uB + (uint32_t)bp * 16 * ROWB + kb);
            }
        }
    }

    // Epilogue in log2-domain: K = exp2(f2*d - (hi+hj)); the max(l2,0) clamp
    // is dropped (only affects diagonal noise ~1e-5 in arg — negligible).
    const float LG2E = 1.4426950408889634f;
    float clg = g_scale * LG2E;
    float f2  = 2.0f * clg;
    int r0 = wy * 64 + (lane >> 2);
    int c0 = wx * 32 + 2 * (lane & 3);

    float hi[8], hj[8];
    #pragma unroll
    for (int mt = 0; mt < 4; mt++) {
        hi[mt * 2]     = clg * sqa[r0 + mt * 16];
        hi[mt * 2 + 1] = clg * sqa[r0 + mt * 16 + 8];
    }
    #pragma unroll
    for (int nt = 0; nt < 4; nt++) {
        hj[nt * 2]     = clg * sqb[c0 + nt * 8];
        hj[nt * 2 + 1] = clg * sqb[c0 + nt * 8 + 1];
    }

    float psum[4] = {0.0f, 0.0f, 0.0f, 0.0f};
    #pragma unroll
    for (int mt = 0; mt < 4; mt++) {
        #pragma unroll
        for (int nt = 0; nt < 4; nt++) {
            #pragma unroll
            for (int e = 0; e < 4; e++) {
                float d   = acc[mt][nt][e];
                float arg = fmaf(f2, d,
                                 -(hi[mt * 2 + (e >> 1)] + hj[nt * 2 + (e & 1)]));
                float e1  = ex2f(arg);
                float e2  = e1 * e1;
                float e4  = e2 * e2;
                float e8  = e4 * e4;
                float e16 = e8 * e8;
                psum[mt] += ((e1 + e2) + (e4 + e8)) + e16;
            }
        }
    }
    double local = (double)((psum[0] + psum[1]) + (psum[2] + psum[3]));

    // Tile weight: sign from halves, x2 for off-diagonal (mirror tile)
    double w = ((bi < NT / 2) == (bj < NT / 2)) ? 1.0 : -1.0;
    if (bj > bi) w *= 2.0;
    local *= w;

    // Warp shfl reduce (double) + one atomic per warp
    #pragma unroll
    for (int s = 16; s > 0; s >>= 1)
        local += __shfl_xor_sync(0xFFFFFFFFu, local, s);
    if (lane == 0) {
        atomicAdd(&g_result, local);
        __threadfence();
    }

    // Fused finalize: last CTA writes the output
    __syncthreads();
    if (tid == 0) {
        unsigned int old = atomicInc(&g_pair_count, NTRI - 1);
        if (old == NTRI - 1) {
            __threadfence();
            double r = *((volatile double*)&g_result);
            out[0] = (float)(r * (1.0 / ((double)BROWS * (double)BROWS)));
        }
    }
}

// ---------------------------------------------------------------------------
extern "C" void kernel_launch(void* const* d_in, const int* in_sizes, int n_in,
                              void* d_out, int out_size) {
    const float* src = (const float*)d_in[0];
    const float* tgt = (const float*)d_in[1];
    float* out = (float*)d_out;
    (void)in_sizes; (void)n_in; (void)out_size;

    cudaFuncSetAttribute(pair13_kernel,
                         cudaFuncAttributeMaxDynamicSharedMemorySize, DYN_SMEM);

    int dev = 0, nsm = 148;
    cudaGetDevice(&dev);
    cudaDeviceGetAttribute(&nsm, cudaDevAttrMultiProcessorCount, dev);

    prep_kernel<<<PREPB, 256>>>(src, tgt);
    pair13_kernel<<<NTRI, 256, DYN_SMEM>>>(out, nsm);
}